// round 10
// baseline (speedup 1.0000x reference)
#include <cuda_runtime.h>
#include <cuda_fp16.h>

#define NN 50000
#define NE 800000
#define FEAT 128
#define HID 64
#define NCLS 12
#define SB 49                         // scan blocks (1024 nodes each)

// ---------------- scratch (static device globals; zero-initialized) ----------
__device__ __align__(16) int     g_deg[NN];                  // zero-invariant
__device__ __align__(16) unsigned long long g_state[SB];     // zero-invariant
__device__ __align__(16) int     g_rowptr[NN + 1];
__device__ __align__(16) int     g_cursor[NN];
__device__ __align__(16) int     g_csr[NE];
__device__ __align__(16) float   g_dinv[NN];
__device__ __align__(16) __half2 g_xws[NN * (HID / 2)];   // layer-1 (A@W1)*dinv
__device__ __align__(16) __half2 g_xws2[NN * (HID / 2)];  // layer-2 (h1@W2)*dinv
__device__ __align__(16) __half  g_w1t[64 * FEAT];        // W1^T fp16 (n-major)
__device__ __align__(16) __half  g_w2t[64 * HID];         // W2^T fp16 (n-major)

// ---------------- CSR build + weight conversion ------------------------------
__global__ void k_count(const int* __restrict__ dst,
                        const float* __restrict__ W1, const float* __restrict__ W2) {
    int b = blockIdx.x;
    if (b == gridDim.x - 1) {            // extra block: convert weights to fp16 n-major
        for (int i = threadIdx.x; i < 64 * FEAT; i += 256) {
            int n = i / FEAT, k = i % FEAT;
            g_w1t[i] = __float2half(W1[k * 64 + n]);
        }
        for (int i = threadIdx.x; i < 64 * HID; i += 256) {
            int n = i / HID, k = i % HID;
            g_w2t[i] = __float2half(W2[k * 64 + n]);
        }
        return;
    }
    int e = b * 256 + threadIdx.x;
    if (e < NE) atomicAdd(&g_deg[dst[e]], 1);
}

__device__ __forceinline__ int block_excl_scan(int v, int* sm32) {
    int lane = threadIdx.x & 31, wid = threadIdx.x >> 5;
    int incl = v;
#pragma unroll
    for (int d = 1; d < 32; d <<= 1) {
        int n = __shfl_up_sync(0xffffffffu, incl, d);
        if (lane >= d) incl += n;
    }
    if (lane == 31) sm32[wid] = incl;
    __syncthreads();
    if (wid == 0) {
        int w = sm32[lane];
#pragma unroll
        for (int d = 1; d < 32; d <<= 1) {
            int n = __shfl_up_sync(0xffffffffu, w, d);
            if (lane >= d) w += n;
        }
        sm32[lane] = w;
    }
    __syncthreads();
    int off = wid ? sm32[wid - 1] : 0;
    return incl - v + off;
}

// single-pass scan via decoupled aggregates
__global__ void __launch_bounds__(1024)
k_scan() {
    __shared__ int sm32[32];
    __shared__ int s_base;
    int tid = threadIdx.x, b = blockIdx.x;
    int i = b * 1024 + tid;
    int v = (i < NN) ? g_deg[i] : 0;
    int excl = block_excl_scan(v, sm32);
    if (tid == 1023) {
        unsigned long long st = (1ULL << 32) | (unsigned)(excl + v);
        atomicExch(&g_state[b], st);
    }
    if (tid < 32) {
        unsigned sum = 0;
        for (int j = tid; j < b; j += 32) {
            unsigned long long s;
            do { s = atomicAdd(&g_state[j], 0ULL); } while (!(s >> 32));
            sum += (unsigned)s;
        }
#pragma unroll
        for (int d = 16; d; d >>= 1) sum += __shfl_xor_sync(0xffffffffu, sum, d);
        if (tid == 0) s_base = (int)sum;
    }
    __syncthreads();
    if (i < NN) {
        int run = s_base + excl;
        g_rowptr[i] = run;
        g_cursor[i] = run;
        g_dinv[i]   = rsqrtf((float)v + 1.0f);
    }
    if (b == 0 && tid == 0) g_rowptr[NN] = NE;
}

// fill CSR; restore zero-invariants for the next replay
__global__ void k_fill(const int* __restrict__ src,
                       const int* __restrict__ dst) {
    int e = blockIdx.x * blockDim.x + threadIdx.x;
    if (e < NN) g_deg[e] = 0;
    if (e < SB) g_state[e] = 0ULL;
    if (e < NE) {
        int d = dst[e];
        int pos = atomicAdd(&g_cursor[d], 1);
        g_csr[pos] = src[e];
    }
}

// ---------------- mma / ldmatrix helpers -------------------------------------
__device__ __forceinline__ void mma16816(float c[4],
                                         unsigned a0, unsigned a1, unsigned a2, unsigned a3,
                                         unsigned b0, unsigned b1) {
    asm volatile(
        "mma.sync.aligned.m16n8k16.row.col.f32.f16.f16.f32 "
        "{%0,%1,%2,%3}, {%4,%5,%6,%7}, {%8,%9}, {%0,%1,%2,%3};\n"
        : "+f"(c[0]), "+f"(c[1]), "+f"(c[2]), "+f"(c[3])
        : "r"(a0), "r"(a1), "r"(a2), "r"(a3), "r"(b0), "r"(b1));
}

__device__ __forceinline__ void ldsm4(unsigned& a0, unsigned& a1,
                                      unsigned& a2, unsigned& a3, unsigned addr) {
    asm volatile(
        "ldmatrix.sync.aligned.m8n8.x4.shared.b16 {%0,%1,%2,%3}, [%4];\n"
        : "=r"(a0), "=r"(a1), "=r"(a2), "=r"(a3) : "r"(addr));
}

// ---------------- GEMM1: g_xws = (x @ W1) * dinv  (tensor cores) -------------
__global__ void __launch_bounds__(256)
k_gemm1(const float* __restrict__ Aext) {
    const int K = FEAT;
    const int KP = 64 + 8;              // Ah row pitch (halfs)
    __shared__ __half Ah[64 * KP];
    int tid = threadIdx.x;
    int lane = tid & 31, warp = tid >> 5;
    int row0 = blockIdx.x * 64;
    int gid = lane >> 2, tig = lane & 3;
    int n0 = warp * 8;

    const int NK = K / 16;
    unsigned bf[NK][2];
#pragma unroll
    for (int kk = 0; kk < NK; kk++) {
        const __half* wb = &g_w1t[(n0 + gid) * K + kk * 16 + tig * 2];
        bf[kk][0] = *(const unsigned*)wb;
        bf[kk][1] = *(const unsigned*)(wb + 8);
    }

    float cacc[4][4];
#pragma unroll
    for (int r = 0; r < 4; r++)
        cacc[r][0] = cacc[r][1] = cacc[r][2] = cacc[r][3] = 0.f;

    const int NCH = K / 64;
    float4 vf[4];
#pragma unroll
    for (int p = 0; p < 4; p++) {
        int i = tid + p * 256;
        int r = i >> 4, c4 = i & 15;
        vf[p] = (row0 + r < NN)
            ? *(const float4*)&Aext[(size_t)(row0 + r) * K + c4 * 4]
            : make_float4(0.f, 0.f, 0.f, 0.f);
    }

    unsigned abase = (unsigned)__cvta_generic_to_shared(
        &Ah[(lane & 15) * KP + (lane >> 4) * 8]);

#pragma unroll
    for (int ch = 0; ch < NCH; ch++) {
#pragma unroll
        for (int p = 0; p < 4; p++) {
            int i = tid + p * 256;
            int r = i >> 4, c4 = i & 15;
            __half2 h0 = __floats2half2_rn(vf[p].x, vf[p].y);
            __half2 h1 = __floats2half2_rn(vf[p].z, vf[p].w);
            *(unsigned*)&Ah[r * KP + c4 * 4]     = *(unsigned*)&h0;
            *(unsigned*)&Ah[r * KP + c4 * 4 + 2] = *(unsigned*)&h1;
        }
        __syncthreads();

        if (ch + 1 < NCH) {
#pragma unroll
            for (int p = 0; p < 4; p++) {
                int i = tid + p * 256;
                int r = i >> 4, c4 = i & 15;
                vf[p] = (row0 + r < NN)
                    ? *(const float4*)&Aext[(size_t)(row0 + r) * K + (ch + 1) * 64 + c4 * 4]
                    : make_float4(0.f, 0.f, 0.f, 0.f);
            }
        }

#pragma unroll
        for (int kk = 0; kk < 4; kk++) {
            int kf = ch * 4 + kk;
            int kl = kk * 16;
#pragma unroll
            for (int rt = 0; rt < 4; rt++) {
                unsigned a0, a1, a2, a3;
                ldsm4(a0, a1, a2, a3,
                      abase + (unsigned)((rt * 16 * KP + kl) * sizeof(__half)));
                mma16816(cacc[rt], a0, a1, a2, a3, bf[kf][0], bf[kf][1]);
            }
        }
        if (ch + 1 < NCH) __syncthreads();
    }

#pragma unroll
    for (int rt = 0; rt < 4; rt++) {
        int r0 = row0 + rt * 16 + gid;
        int r1 = r0 + 8;
        if (r0 < NN) {
            float dv = g_dinv[r0];
            g_xws[r0 * 32 + n0 / 2 + tig] =
                __floats2half2_rn(cacc[rt][0] * dv, cacc[rt][1] * dv);
        }
        if (r1 < NN) {
            float dv = g_dinv[r1];
            g_xws[r1 * 32 + n0 / 2 + tig] =
                __floats2half2_rn(cacc[rt][2] * dv, cacc[rt][3] * dv);
        }
    }
}

// ---------------- aggregation helper: warp per dst node ----------------------
__device__ __forceinline__ void agg_row(const __half2* __restrict__ tab,
                                        int node, int lane, float& a0, float& a1) {
    int beg = g_rowptr[node];
    int end = g_rowptr[node + 1];
    a0 = 0.f; a1 = 0.f;
    for (int base = beg; base < end; base += 32) {
        int idx = base + lane;
        int s_l = (idx < end) ? g_csr[idx] : 0;
        int iters = end - base;
        if (iters > 32) iters = 32;
#pragma unroll 4
        for (int j = 0; j < iters; j++) {
            int s = __shfl_sync(0xffffffffu, s_l, j);
            float2 v = __half22float2(tab[s * (HID / 2) + lane]);
            a0 += v.x;
            a1 += v.y;
        }
    }
}

// ---------------- fused layer-1 aggregation + GEMM2 --------------------------
// Block: 512 threads = 16 warps; warp w aggregates node row0+w, h1 tile in smem,
// then warps 0-7 do the 16x64 @ 64x64 tensor GEMM (+*dinv) -> g_xws2.
__global__ void __launch_bounds__(512)
k_aggmm(const float* __restrict__ b1) {
    const int KP = 72;                  // h1 tile pitch (halfs)
    __shared__ __half Ht[16 * KP];
    int tid = threadIdx.x, lane = tid & 31, warp = tid >> 5;
    int row0 = blockIdx.x * 16;
    int node = row0 + warp;             // NN = 16*3125, always in range
    int gid = lane >> 2, tig = lane & 3;

    // W2 B-fragments for mma warps (registers, L2-cached)
    unsigned bf[4][2];
    if (warp < 8) {
#pragma unroll
        for (int kk = 0; kk < 4; kk++) {
            const __half* wb = &g_w2t[(warp * 8 + gid) * HID + kk * 16 + tig * 2];
            bf[kk][0] = *(const unsigned*)wb;
            bf[kk][1] = *(const unsigned*)(wb + 8);
        }
    }

    // layer-1 aggregation epilogue: h1 = relu(dinv*(agg + self) + b1)
    float a0, a1;
    agg_row(g_xws, node, lane, a0, a1);
    float dd = g_dinv[node];
    float2 sv = __half22float2(g_xws[node * 32 + lane]);
    float r0 = fmaxf(fmaf(dd, a0 + sv.x, b1[2 * lane + 0]), 0.f);
    float r1 = fmaxf(fmaf(dd, a1 + sv.y, b1[2 * lane + 1]), 0.f);
    *(__half2*)&Ht[warp * KP + 2 * lane] = __floats2half2_rn(r0, r1);
    __syncthreads();

    // GEMM2: 16x64 tile @ W2 (64x64) -> *dinv -> g_xws2
    if (warp < 8) {
        float cacc[4] = {0.f, 0.f, 0.f, 0.f};
        unsigned abase = (unsigned)__cvta_generic_to_shared(
            &Ht[(lane & 15) * KP + (lane >> 4) * 8]);
#pragma unroll
        for (int kk = 0; kk < 4; kk++) {
            unsigned a0_, a1_, a2_, a3_;
            ldsm4(a0_, a1_, a2_, a3_, abase + (unsigned)(kk * 16 * sizeof(__half)));
            mma16816(cacc, a0_, a1_, a2_, a3_, bf[kk][0], bf[kk][1]);
        }
        int r0i = row0 + gid, r1i = r0i + 8;
        float dv0 = g_dinv[r0i], dv1 = g_dinv[r1i];
        g_xws2[r0i * 32 + warp * 4 + tig] = __floats2half2_rn(cacc[0] * dv0, cacc[1] * dv0);
        g_xws2[r1i * 32 + warp * 4 + tig] = __floats2half2_rn(cacc[2] * dv1, cacc[3] * dv1);
    }
}

// ---------------- layer-2 aggregation + FC -> out ----------------------------
__global__ void k_agg2(const float* __restrict__ b2, const float* __restrict__ Wfc,
                       const float* __restrict__ bfc, float* __restrict__ out) {
    __shared__ float sW[HID * NCLS];
    __shared__ float sb2[HID];
    __shared__ float sbfc[NCLS];
    int tid = threadIdx.x;
    for (int i = tid; i < HID * NCLS; i += 256) sW[i] = Wfc[i];
    if (tid < HID)  sb2[tid]  = b2[tid];
    if (tid < NCLS) sbfc[tid] = bfc[tid];
    __syncthreads();

    int warp = (blockIdx.x * blockDim.x + tid) >> 5;
    int lane = tid & 31;
    if (warp >= NN) return;
    float a0, a1;
    agg_row(g_xws2, warp, lane, a0, a1);
    float dd = g_dinv[warp];
    float2 sv = __half22float2(g_xws2[warp * (HID / 2) + lane]);
    float t0 = fmaxf(fmaf(dd, a0 + sv.x, sb2[2 * lane + 0]), 0.f);
    float t1 = fmaxf(fmaf(dd, a1 + sv.y, sb2[2 * lane + 1]), 0.f);

    float res = 0.f;
#pragma unroll
    for (int c = 0; c < NCLS; c++) {
        float p = t0 * sW[(2 * lane + 0) * NCLS + c] + t1 * sW[(2 * lane + 1) * NCLS + c];
        p += __shfl_xor_sync(0xffffffffu, p, 16);
        p += __shfl_xor_sync(0xffffffffu, p, 8);
        p += __shfl_xor_sync(0xffffffffu, p, 4);
        p += __shfl_xor_sync(0xffffffffu, p, 2);
        p += __shfl_xor_sync(0xffffffffu, p, 1);
        if (lane == c) res = p + sbfc[c];
    }
    if (lane < NCLS) out[warp * NCLS + lane] = res;
}

// ---------------- launch -----------------------------------------------------
extern "C" void kernel_launch(void* const* d_in, const int* in_sizes, int n_in,
                              void* d_out, int out_size) {
    const float* x   = (const float*)d_in[0];
    const int*   ei  = (const int*)d_in[1];   // int32 (JAX x64-disabled)
    const float* W1  = (const float*)d_in[2];
    const float* b1  = (const float*)d_in[3];
    const float* W2  = (const float*)d_in[4];
    const float* b2  = (const float*)d_in[5];
    const float* Wfc = (const float*)d_in[6];
    const float* bfc = (const float*)d_in[7];
    float* out = (float*)d_out;
    const int* srcp = ei;
    const int* dstp = ei + NE;

    k_count<<<(NE + 255) / 256 + 1, 256>>>(dstp, W1, W2);  // count + W->fp16
    k_scan<<<SB, 1024>>>();
    k_fill<<<(NE + 255) / 256, 256>>>(srcp, dstp);

    k_gemm1<<<(NN + 63) / 64, 256>>>(x);                   // -> g_xws
    k_aggmm<<<NN / 16, 512>>>(b1);                         // agg1 + gemm2 -> g_xws2
    k_agg2<<<(NN + 7) / 8, 256>>>(b2, Wfc, bfc, out);      // -> d_out
}

// round 11
// speedup vs baseline: 1.1646x; 1.1646x over previous
#include <cuda_runtime.h>
#include <cuda_fp16.h>

#define NN 50000
#define NE 800000
#define FEAT 128
#define HID 64
#define NCLS 12
#define SB 49                         // scan blocks (1024 nodes each)
#define GB1 ((NN + 63) / 64)          // gemm1 blocks: 782
#define FBLK ((NE + 255) / 256)       // fill blocks: 3125

// ---------------- scratch (static device globals; zero-initialized) ----------
__device__ __align__(16) int     g_deg[NN];                  // zero-invariant
__device__ __align__(16) unsigned long long g_state[SB];     // zero-invariant
__device__ __align__(16) int     g_rowptr[NN + 1];
__device__ __align__(16) int     g_cursor[NN];
__device__ __align__(16) int     g_csr[NE];
__device__ __align__(16) float   g_dinv[NN];
__device__ __align__(16) __half2 g_xws[NN * (HID / 2)];   // (A@W)*dinv fp16 per layer
__device__ __align__(16) __half2 g_h1[NN * (HID / 2)];    // layer-1 activations (fp16)
__device__ __align__(16) __half  g_w1t[64 * FEAT];        // W1^T fp16 (n-major)
__device__ __align__(16) __half  g_w2t[64 * HID];         // W2^T fp16 (n-major)

// ---------------- CSR count + weight conversion ------------------------------
__global__ void k_count(const int* __restrict__ dst,
                        const float* __restrict__ W1, const float* __restrict__ W2) {
    int b = blockIdx.x;
    if (b == gridDim.x - 1) {            // extra block: convert weights to fp16 n-major
        for (int i = threadIdx.x; i < 64 * FEAT; i += 256) {
            int n = i / FEAT, k = i % FEAT;
            g_w1t[i] = __float2half(W1[k * 64 + n]);
        }
        for (int i = threadIdx.x; i < 64 * HID; i += 256) {
            int n = i / HID, k = i % HID;
            g_w2t[i] = __float2half(W2[k * 64 + n]);
        }
        return;
    }
    int e = b * 256 + threadIdx.x;
    if (e < NE) atomicAdd(&g_deg[dst[e]], 1);
}

__device__ __forceinline__ int block_excl_scan(int v, int* sm32) {
    int lane = threadIdx.x & 31, wid = threadIdx.x >> 5;
    int incl = v;
#pragma unroll
    for (int d = 1; d < 32; d <<= 1) {
        int n = __shfl_up_sync(0xffffffffu, incl, d);
        if (lane >= d) incl += n;
    }
    if (lane == 31) sm32[wid] = incl;
    __syncthreads();
    if (wid == 0) {
        int w = sm32[lane];
#pragma unroll
        for (int d = 1; d < 32; d <<= 1) {
            int n = __shfl_up_sync(0xffffffffu, w, d);
            if (lane >= d) w += n;
        }
        sm32[lane] = w;
    }
    __syncthreads();
    int off = wid ? sm32[wid - 1] : 0;
    return incl - v + off;
}

// single-pass scan via decoupled aggregates
__global__ void __launch_bounds__(1024)
k_scan() {
    __shared__ int sm32[32];
    __shared__ int s_base;
    int tid = threadIdx.x, b = blockIdx.x;
    int i = b * 1024 + tid;
    int v = (i < NN) ? g_deg[i] : 0;
    int excl = block_excl_scan(v, sm32);
    if (tid == 1023) {
        unsigned long long st = (1ULL << 32) | (unsigned)(excl + v);
        atomicExch(&g_state[b], st);
    }
    if (tid < 32) {
        unsigned sum = 0;
        for (int j = tid; j < b; j += 32) {
            unsigned long long s;
            do { s = atomicAdd(&g_state[j], 0ULL); } while (!(s >> 32));
            sum += (unsigned)s;
        }
#pragma unroll
        for (int d = 16; d; d >>= 1) sum += __shfl_xor_sync(0xffffffffu, sum, d);
        if (tid == 0) s_base = (int)sum;
    }
    __syncthreads();
    if (i < NN) {
        int run = s_base + excl;
        g_rowptr[i] = run;
        g_cursor[i] = run;
        g_dinv[i]   = rsqrtf((float)v + 1.0f);
    }
    if (b == 0 && tid == 0) g_rowptr[NN] = NE;
}

// ---------------- mma / ldmatrix helpers -------------------------------------
__device__ __forceinline__ void mma16816(float c[4],
                                         unsigned a0, unsigned a1, unsigned a2, unsigned a3,
                                         unsigned b0, unsigned b1) {
    asm volatile(
        "mma.sync.aligned.m16n8k16.row.col.f32.f16.f16.f32 "
        "{%0,%1,%2,%3}, {%4,%5,%6,%7}, {%8,%9}, {%0,%1,%2,%3};\n"
        : "+f"(c[0]), "+f"(c[1]), "+f"(c[2]), "+f"(c[3])
        : "r"(a0), "r"(a1), "r"(a2), "r"(a3), "r"(b0), "r"(b1));
}

__device__ __forceinline__ void ldsm4(unsigned& a0, unsigned& a1,
                                      unsigned& a2, unsigned& a3, unsigned addr) {
    asm volatile(
        "ldmatrix.sync.aligned.m8n8.x4.shared.b16 {%0,%1,%2,%3}, [%4];\n"
        : "=r"(a0), "=r"(a1), "=r"(a2), "=r"(a3) : "r"(addr));
}

// ---------------- GEMM1 body (x @ W1)*dinv, full-prefetch both K-chunks ------
__device__ __forceinline__ void gemm1_body(const float* __restrict__ Aext, int bidx) {
    const int K = FEAT;
    const int KP = 64 + 8;
    __shared__ __half Ah[64 * KP];
    int tid = threadIdx.x;
    int lane = tid & 31, warp = tid >> 5;
    int row0 = bidx * 64;
    int gid = lane >> 2, tig = lane & 3;
    int n0 = warp * 8;

    // issue ALL A loads up-front (8 LDG.128 in flight per thread)
    float4 vf[8];
#pragma unroll
    for (int p = 0; p < 8; p++) {
        int i = tid + (p & 3) * 256;
        int r = i >> 4, c4 = i & 15;
        int col = (p >> 2) * 64 + c4 * 4;
        vf[p] = (row0 + r < NN)
            ? *(const float4*)&Aext[(size_t)(row0 + r) * K + col]
            : make_float4(0.f, 0.f, 0.f, 0.f);
    }

    unsigned bf[8][2];
#pragma unroll
    for (int kk = 0; kk < 8; kk++) {
        const __half* wb = &g_w1t[(n0 + gid) * K + kk * 16 + tig * 2];
        bf[kk][0] = *(const unsigned*)wb;
        bf[kk][1] = *(const unsigned*)(wb + 8);
    }

    float cacc[4][4];
#pragma unroll
    for (int r = 0; r < 4; r++)
        cacc[r][0] = cacc[r][1] = cacc[r][2] = cacc[r][3] = 0.f;

    unsigned abase = (unsigned)__cvta_generic_to_shared(
        &Ah[(lane & 15) * KP + (lane >> 4) * 8]);

#pragma unroll
    for (int ch = 0; ch < 2; ch++) {
        if (ch) __syncthreads();        // protect smem reuse
#pragma unroll
        for (int p = 0; p < 4; p++) {
            int i = tid + p * 256;
            int r = i >> 4, c4 = i & 15;
            float4 v = vf[ch * 4 + p];
            __half2 h0 = __floats2half2_rn(v.x, v.y);
            __half2 h1 = __floats2half2_rn(v.z, v.w);
            *(unsigned*)&Ah[r * KP + c4 * 4]     = *(unsigned*)&h0;
            *(unsigned*)&Ah[r * KP + c4 * 4 + 2] = *(unsigned*)&h1;
        }
        __syncthreads();
#pragma unroll
        for (int kk = 0; kk < 4; kk++) {
            int kf = ch * 4 + kk;
            int kl = kk * 16;
#pragma unroll
            for (int rt = 0; rt < 4; rt++) {
                unsigned a0, a1, a2, a3;
                ldsm4(a0, a1, a2, a3,
                      abase + (unsigned)((rt * 16 * KP + kl) * sizeof(__half)));
                mma16816(cacc[rt], a0, a1, a2, a3, bf[kf][0], bf[kf][1]);
            }
        }
    }

#pragma unroll
    for (int rt = 0; rt < 4; rt++) {
        int r0 = row0 + rt * 16 + gid;
        int r1 = r0 + 8;
        if (r0 < NN) {
            float dv = g_dinv[r0];
            g_xws[r0 * 32 + n0 / 2 + tig] =
                __floats2half2_rn(cacc[rt][0] * dv, cacc[rt][1] * dv);
        }
        if (r1 < NN) {
            float dv = g_dinv[r1];
            g_xws[r1 * 32 + n0 / 2 + tig] =
                __floats2half2_rn(cacc[rt][2] * dv, cacc[rt][3] * dv);
        }
    }
}

// ---------------- merged: gemm1 blocks + CSR-fill blocks ---------------------
// Blocks [0, GB1): gemm1 (DRAM-stream). Blocks [GB1, GB1+FBLK): fill (scatter).
// Both depend only on k_scan outputs; overlapping hides the scatter latency.
__global__ void __launch_bounds__(256)
k_fillgemm(const int* __restrict__ src, const int* __restrict__ dst,
           const float* __restrict__ x) {
    if (blockIdx.x < GB1) {
        gemm1_body(x, blockIdx.x);
        return;
    }
    int e = (blockIdx.x - GB1) * 256 + threadIdx.x;
    if (e < NN) g_deg[e] = 0;           // restore zero-invariants
    if (e < SB) g_state[e] = 0ULL;
    if (e < NE) {
        int d = dst[e];
        int pos = atomicAdd(&g_cursor[d], 1);
        g_csr[pos] = src[e];
    }
}

// ---------------- GEMM2: g_xws = (h1 @ W2) * dinv ---------------------------
__global__ void __launch_bounds__(256)
k_gemm2() {
    const int K = HID;
    const int KP = 64 + 8;
    __shared__ __half Ah[64 * KP];
    int tid = threadIdx.x;
    int lane = tid & 31, warp = tid >> 5;
    int row0 = blockIdx.x * 64;
    int gid = lane >> 2, tig = lane & 3;
    int n0 = warp * 8;

    unsigned vh[8];
#pragma unroll
    for (int p = 0; p < 8; p++) {
        int i = tid + p * 256;
        int r = i >> 5, c = i & 31;
        vh[p] = (row0 + r < NN) ? *(const unsigned*)&g_h1[(row0 + r) * 32 + c] : 0u;
    }

    unsigned bf[4][2];
#pragma unroll
    for (int kk = 0; kk < 4; kk++) {
        const __half* wb = &g_w2t[(n0 + gid) * K + kk * 16 + tig * 2];
        bf[kk][0] = *(const unsigned*)wb;
        bf[kk][1] = *(const unsigned*)(wb + 8);
    }

    float cacc[4][4];
#pragma unroll
    for (int r = 0; r < 4; r++)
        cacc[r][0] = cacc[r][1] = cacc[r][2] = cacc[r][3] = 0.f;

#pragma unroll
    for (int p = 0; p < 8; p++) {
        int i = tid + p * 256;
        int r = i >> 5, c = i & 31;
        *(unsigned*)&Ah[r * KP + c * 2] = vh[p];
    }
    __syncthreads();

    unsigned abase = (unsigned)__cvta_generic_to_shared(
        &Ah[(lane & 15) * KP + (lane >> 4) * 8]);
#pragma unroll
    for (int kk = 0; kk < 4; kk++) {
        int kl = kk * 16;
#pragma unroll
        for (int rt = 0; rt < 4; rt++) {
            unsigned a0, a1, a2, a3;
            ldsm4(a0, a1, a2, a3,
                  abase + (unsigned)((rt * 16 * KP + kl) * sizeof(__half)));
            mma16816(cacc[rt], a0, a1, a2, a3, bf[kk][0], bf[kk][1]);
        }
    }

#pragma unroll
    for (int rt = 0; rt < 4; rt++) {
        int r0 = row0 + rt * 16 + gid;
        int r1 = r0 + 8;
        if (r0 < NN) {
            float dv = g_dinv[r0];
            g_xws[r0 * 32 + n0 / 2 + tig] =
                __floats2half2_rn(cacc[rt][0] * dv, cacc[rt][1] * dv);
        }
        if (r1 < NN) {
            float dv = g_dinv[r1];
            g_xws[r1 * 32 + n0 / 2 + tig] =
                __floats2half2_rn(cacc[rt][2] * dv, cacc[rt][3] * dv);
        }
    }
}

// ---------------- aggregation: warp per dst node ----------------------------
__device__ __forceinline__ void agg_row(int node, int lane, float& a0, float& a1) {
    int beg = g_rowptr[node];
    int end = g_rowptr[node + 1];
    a0 = 0.f; a1 = 0.f;
    for (int base = beg; base < end; base += 32) {
        int idx = base + lane;
        int s_l = (idx < end) ? g_csr[idx] : 0;
        int iters = end - base;
        if (iters > 32) iters = 32;
#pragma unroll 4
        for (int j = 0; j < iters; j++) {
            int s = __shfl_sync(0xffffffffu, s_l, j);
            float2 v = __half22float2(g_xws[s * (HID / 2) + lane]);
            a0 += v.x;
            a1 += v.y;
        }
    }
}

__global__ void k_agg1(const float* __restrict__ b1) {
    int warp = (blockIdx.x * blockDim.x + threadIdx.x) >> 5;
    int lane = threadIdx.x & 31;
    if (warp >= NN) return;
    float a0, a1;
    agg_row(warp, lane, a0, a1);
    float dd = g_dinv[warp];
    float2 sv = __half22float2(g_xws[warp * (HID / 2) + lane]);
    float r0 = fmaxf(fmaf(dd, a0 + sv.x, b1[2 * lane + 0]), 0.f);
    float r1 = fmaxf(fmaf(dd, a1 + sv.y, b1[2 * lane + 1]), 0.f);
    g_h1[warp * (HID / 2) + lane] = __floats2half2_rn(r0, r1);
}

__global__ void k_agg2(const float* __restrict__ b2, const float* __restrict__ Wfc,
                       const float* __restrict__ bfc, float* __restrict__ out) {
    __shared__ float sW[HID * NCLS];
    __shared__ float sb2[HID];
    __shared__ float sbfc[NCLS];
    int tid = threadIdx.x;
    for (int i = tid; i < HID * NCLS; i += 256) sW[i] = Wfc[i];
    if (tid < HID)  sb2[tid]  = b2[tid];
    if (tid < NCLS) sbfc[tid] = bfc[tid];
    __syncthreads();

    int warp = (blockIdx.x * blockDim.x + tid) >> 5;
    int lane = tid & 31;
    if (warp >= NN) return;
    float a0, a1;
    agg_row(warp, lane, a0, a1);
    float dd = g_dinv[warp];
    float2 sv = __half22float2(g_xws[warp * (HID / 2) + lane]);
    float t0 = fmaxf(fmaf(dd, a0 + sv.x, sb2[2 * lane + 0]), 0.f);
    float t1 = fmaxf(fmaf(dd, a1 + sv.y, sb2[2 * lane + 1]), 0.f);

    float res = 0.f;
#pragma unroll
    for (int c = 0; c < NCLS; c++) {
        float p = t0 * sW[(2 * lane + 0) * NCLS + c] + t1 * sW[(2 * lane + 1) * NCLS + c];
        p += __shfl_xor_sync(0xffffffffu, p, 16);
        p += __shfl_xor_sync(0xffffffffu, p, 8);
        p += __shfl_xor_sync(0xffffffffu, p, 4);
        p += __shfl_xor_sync(0xffffffffu, p, 2);
        p += __shfl_xor_sync(0xffffffffu, p, 1);
        if (lane == c) res = p + sbfc[c];
    }
    if (lane < NCLS) out[warp * NCLS + lane] = res;
}

// ---------------- launch -----------------------------------------------------
extern "C" void kernel_launch(void* const* d_in, const int* in_sizes, int n_in,
                              void* d_out, int out_size) {
    const float* x   = (const float*)d_in[0];
    const int*   ei  = (const int*)d_in[1];   // int32 (JAX x64-disabled)
    const float* W1  = (const float*)d_in[2];
    const float* b1  = (const float*)d_in[3];
    const float* W2  = (const float*)d_in[4];
    const float* b2  = (const float*)d_in[5];
    const float* Wfc = (const float*)d_in[6];
    const float* bfc = (const float*)d_in[7];
    float* out = (float*)d_out;
    const int* srcp = ei;
    const int* dstp = ei + NE;

    k_count<<<FBLK + 1, 256>>>(dstp, W1, W2);        // count + W->fp16
    k_scan<<<SB, 1024>>>();
    k_fillgemm<<<GB1 + FBLK, 256>>>(srcp, dstp, x);  // gemm1 ∥ CSR fill
    k_agg1<<<(NN + 7) / 8, 256>>>(b1);               // -> g_h1 (fp16)
    k_gemm2<<<GB1, 256>>>();                         // -> g_xws (fp16)
    k_agg2<<<(NN + 7) / 8, 256>>>(b2, Wfc, bfc, out);
}

// round 13
// speedup vs baseline: 1.2354x; 1.0608x over previous
#include <cuda_runtime.h>
#include <cuda_fp16.h>

#define NN 50000
#define NE 800000
#define FEAT 128
#define HID 64
#define NCLS 12
#define SB 49                         // scan blocks (1024 nodes each)
#define GB1 ((NN + 63) / 64)          // gemm1 blocks: 782
#define FBLK ((NE + 255) / 256)       // fill blocks: 3125
#define ZOFF ((unsigned)(NN * 128))   // byte offset of the always-zero pad row

// ---------------- scratch (static device globals; zero-initialized) ----------
__device__ __align__(16) int      g_deg[NN];                 // zero-invariant
__device__ __align__(16) unsigned long long g_state[SB];     // zero-invariant
__device__ __align__(16) int      g_rowptr[NN + 1];
__device__ __align__(16) int      g_cursor[NN];
__device__ __align__(16) unsigned g_csrb[NE];                // src row BYTE offsets
__device__ __align__(16) float    g_dinv[NN];
__device__ __align__(16) __half2  g_xws[(NN + 1) * (HID / 2)]; // +1 zero pad row
__device__ __align__(16) __half2  g_h1[NN * (HID / 2)];      // layer-1 activations
__device__ __align__(16) __half   g_w1t[64 * FEAT];          // W1^T fp16 (n-major)
__device__ __align__(16) __half   g_w2t[64 * HID];           // W2^T fp16 (n-major)

// ---------------- CSR count + weight conversion ------------------------------
__global__ void k_count(const int* __restrict__ dst,
                        const float* __restrict__ W1, const float* __restrict__ W2) {
    int b = blockIdx.x;
    if (b == gridDim.x - 1) {            // extra block: convert weights to fp16 n-major
        for (int i = threadIdx.x; i < 64 * FEAT; i += 256) {
            int n = i / FEAT, k = i % FEAT;
            g_w1t[i] = __float2half(W1[k * 64 + n]);
        }
        for (int i = threadIdx.x; i < 64 * HID; i += 256) {
            int n = i / HID, k = i % HID;
            g_w2t[i] = __float2half(W2[k * 64 + n]);
        }
        return;
    }
    int e = b * 256 + threadIdx.x;
    if (e < NE) atomicAdd(&g_deg[dst[e]], 1);
}

__device__ __forceinline__ int block_excl_scan(int v, int* sm32) {
    int lane = threadIdx.x & 31, wid = threadIdx.x >> 5;
    int incl = v;
#pragma unroll
    for (int d = 1; d < 32; d <<= 1) {
        int n = __shfl_up_sync(0xffffffffu, incl, d);
        if (lane >= d) incl += n;
    }
    if (lane == 31) sm32[wid] = incl;
    __syncthreads();
    if (wid == 0) {
        int w = sm32[lane];
#pragma unroll
        for (int d = 1; d < 32; d <<= 1) {
            int n = __shfl_up_sync(0xffffffffu, w, d);
            if (lane >= d) w += n;
        }
        sm32[lane] = w;
    }
    __syncthreads();
    int off = wid ? sm32[wid - 1] : 0;
    return incl - v + off;
}

// single-pass scan via decoupled aggregates
__global__ void __launch_bounds__(1024)
k_scan() {
    __shared__ int sm32[32];
    __shared__ int s_base;
    int tid = threadIdx.x, b = blockIdx.x;
    int i = b * 1024 + tid;
    int v = (i < NN) ? g_deg[i] : 0;
    int excl = block_excl_scan(v, sm32);
    if (tid == 1023) {
        unsigned long long st = (1ULL << 32) | (unsigned)(excl + v);
        atomicExch(&g_state[b], st);
    }
    if (tid < 32) {
        unsigned sum = 0;
        for (int j = tid; j < b; j += 32) {
            unsigned long long s;
            do { s = atomicAdd(&g_state[j], 0ULL); } while (!(s >> 32));
            sum += (unsigned)s;
        }
#pragma unroll
        for (int d = 16; d; d >>= 1) sum += __shfl_xor_sync(0xffffffffu, sum, d);
        if (tid == 0) s_base = (int)sum;
    }
    __syncthreads();
    if (i < NN) {
        int run = s_base + excl;
        g_rowptr[i] = run;
        g_cursor[i] = run;
        g_dinv[i]   = rsqrtf((float)v + 1.0f);
    }
    if (b == 0 && tid == 0) g_rowptr[NN] = NE;
}

// ---------------- mma / ldmatrix helpers -------------------------------------
__device__ __forceinline__ void mma16816(float c[4],
                                         unsigned a0, unsigned a1, unsigned a2, unsigned a3,
                                         unsigned b0, unsigned b1) {
    asm volatile(
        "mma.sync.aligned.m16n8k16.row.col.f32.f16.f16.f32 "
        "{%0,%1,%2,%3}, {%4,%5,%6,%7}, {%8,%9}, {%0,%1,%2,%3};\n"
        : "+f"(c[0]), "+f"(c[1]), "+f"(c[2]), "+f"(c[3])
        : "r"(a0), "r"(a1), "r"(a2), "r"(a3), "r"(b0), "r"(b1));
}

__device__ __forceinline__ void ldsm4(unsigned& a0, unsigned& a1,
                                      unsigned& a2, unsigned& a3, unsigned addr) {
    asm volatile(
        "ldmatrix.sync.aligned.m8n8.x4.shared.b16 {%0,%1,%2,%3}, [%4];\n"
        : "=r"(a0), "=r"(a1), "=r"(a2), "=r"(a3) : "r"(addr));
}

// ---------------- GEMM1 body (x @ W1)*dinv, full-prefetch both K-chunks ------
__device__ __forceinline__ void gemm1_body(const float* __restrict__ Aext, int bidx) {
    const int K = FEAT;
    const int KP = 64 + 8;
    __shared__ __half Ah[64 * KP];
    int tid = threadIdx.x;
    int lane = tid & 31, warp = tid >> 5;
    int row0 = bidx * 64;
    int gid = lane >> 2, tig = lane & 3;
    int n0 = warp * 8;

    float4 vf[8];
#pragma unroll
    for (int p = 0; p < 8; p++) {
        int i = tid + (p & 3) * 256;
        int r = i >> 4, c4 = i & 15;
        int col = (p >> 2) * 64 + c4 * 4;
        vf[p] = (row0 + r < NN)
            ? *(const float4*)&Aext[(size_t)(row0 + r) * K + col]
            : make_float4(0.f, 0.f, 0.f, 0.f);
    }

    unsigned bf[8][2];
#pragma unroll
    for (int kk = 0; kk < 8; kk++) {
        const __half* wb = &g_w1t[(n0 + gid) * K + kk * 16 + tig * 2];
        bf[kk][0] = *(const unsigned*)wb;
        bf[kk][1] = *(const unsigned*)(wb + 8);
    }

    float cacc[4][4];
#pragma unroll
    for (int r = 0; r < 4; r++)
        cacc[r][0] = cacc[r][1] = cacc[r][2] = cacc[r][3] = 0.f;

    unsigned abase = (unsigned)__cvta_generic_to_shared(
        &Ah[(lane & 15) * KP + (lane >> 4) * 8]);

#pragma unroll
    for (int ch = 0; ch < 2; ch++) {
        if (ch) __syncthreads();
#pragma unroll
        for (int p = 0; p < 4; p++) {
            int i = tid + p * 256;
            int r = i >> 4, c4 = i & 15;
            float4 v = vf[ch * 4 + p];
            __half2 h0 = __floats2half2_rn(v.x, v.y);
            __half2 h1 = __floats2half2_rn(v.z, v.w);
            *(unsigned*)&Ah[r * KP + c4 * 4]     = *(unsigned*)&h0;
            *(unsigned*)&Ah[r * KP + c4 * 4 + 2] = *(unsigned*)&h1;
        }
        __syncthreads();
#pragma unroll
        for (int kk = 0; kk < 4; kk++) {
            int kf = ch * 4 + kk;
            int kl = kk * 16;
#pragma unroll
            for (int rt = 0; rt < 4; rt++) {
                unsigned a0, a1, a2, a3;
                ldsm4(a0, a1, a2, a3,
                      abase + (unsigned)((rt * 16 * KP + kl) * sizeof(__half)));
                mma16816(cacc[rt], a0, a1, a2, a3, bf[kf][0], bf[kf][1]);
            }
        }
    }

#pragma unroll
    for (int rt = 0; rt < 4; rt++) {
        int r0 = row0 + rt * 16 + gid;
        int r1 = r0 + 8;
        if (r0 < NN) {
            float dv = g_dinv[r0];
            g_xws[r0 * 32 + n0 / 2 + tig] =
                __floats2half2_rn(cacc[rt][0] * dv, cacc[rt][1] * dv);
        }
        if (r1 < NN) {
            float dv = g_dinv[r1];
            g_xws[r1 * 32 + n0 / 2 + tig] =
                __floats2half2_rn(cacc[rt][2] * dv, cacc[rt][3] * dv);
        }
    }
}

// ---------------- merged: gemm1 blocks + CSR-fill blocks ---------------------
__global__ void __launch_bounds__(256)
k_fillgemm(const int* __restrict__ src, const int* __restrict__ dst,
           const float* __restrict__ x) {
    if (blockIdx.x < GB1) {
        gemm1_body(x, blockIdx.x);
        return;
    }
    int e = (blockIdx.x - GB1) * 256 + threadIdx.x;
    if (e < NN) g_deg[e] = 0;           // restore zero-invariants
    if (e < SB) g_state[e] = 0ULL;
    if (e < NE) {
        int d = dst[e];
        int pos = atomicAdd(&g_cursor[d], 1);
        g_csrb[pos] = (unsigned)src[e] * 128u;   // BYTE offset of src row
    }
}

// ---------------- GEMM2: g_xws = (h1 @ W2) * dinv ---------------------------
__global__ void __launch_bounds__(256)
k_gemm2() {
    const int K = HID;
    const int KP = 64 + 8;
    __shared__ __half Ah[64 * KP];
    int tid = threadIdx.x;
    int lane = tid & 31, warp = tid >> 5;
    int row0 = blockIdx.x * 64;
    int gid = lane >> 2, tig = lane & 3;
    int n0 = warp * 8;

    unsigned vh[8];
#pragma unroll
    for (int p = 0; p < 8; p++) {
        int i = tid + p * 256;
        int r = i >> 5, c = i & 31;
        vh[p] = (row0 + r < NN) ? *(const unsigned*)&g_h1[(row0 + r) * 32 + c] : 0u;
    }

    unsigned bf[4][2];
#pragma unroll
    for (int kk = 0; kk < 4; kk++) {
        const __half* wb = &g_w2t[(n0 + gid) * K + kk * 16 + tig * 2];
        bf[kk][0] = *(const unsigned*)wb;
        bf[kk][1] = *(const unsigned*)(wb + 8);
    }

    float cacc[4][4];
#pragma unroll
    for (int r = 0; r < 4; r++)
        cacc[r][0] = cacc[r][1] = cacc[r][2] = cacc[r][3] = 0.f;

#pragma unroll
    for (int p = 0; p < 8; p++) {
        int i = tid + p * 256;
        int r = i >> 5, c = i & 31;
        *(unsigned*)&Ah[r * KP + c * 2] = vh[p];
    }
    __syncthreads();

    unsigned abase = (unsigned)__cvta_generic_to_shared(
        &Ah[(lane & 15) * KP + (lane >> 4) * 8]);
#pragma unroll
    for (int kk = 0; kk < 4; kk++) {
        int kl = kk * 16;
#pragma unroll
        for (int rt = 0; rt < 4; rt++) {
            unsigned a0, a1, a2, a3;
            ldsm4(a0, a1, a2, a3,
                  abase + (unsigned)((rt * 16 * KP + kl) * sizeof(__half)));
            mma16816(cacc[rt], a0, a1, a2, a3, bf[kk][0], bf[kk][1]);
        }
    }

#pragma unroll
    for (int rt = 0; rt < 4; rt++) {
        int r0 = row0 + rt * 16 + gid;
        int r1 = r0 + 8;
        if (r0 < NN) {
            float dv = g_dinv[r0];
            g_xws[r0 * 32 + n0 / 2 + tig] =
                __floats2half2_rn(cacc[rt][0] * dv, cacc[rt][1] * dv);
        }
        if (r1 < NN) {
            float dv = g_dinv[r1];
            g_xws[r1 * 32 + n0 / 2 + tig] =
                __floats2half2_rn(cacc[rt][2] * dv, cacc[rt][3] * dv);
        }
    }
}

// ---------------- aggregation: warp per dst node, half2 group accumulate -----
// Per-edge: SHFL + IADD + LDG.64 + HADD2 (branch-free via zero-row padding).
__device__ __forceinline__ void agg_row(int node, int lane, float& a0, float& a1) {
    int beg = g_rowptr[node];
    int end = g_rowptr[node + 1];
    const char* basep = (const char*)g_xws + lane * 4;
    float fa0 = 0.f, fa1 = 0.f;
    for (int b32 = beg; b32 < end; b32 += 32) {
        int idx = b32 + lane;
        unsigned off = (idx < end) ? g_csrb[idx] : ZOFF;
        int rem = end - b32;
        if (rem > 32) rem = 32;
        int ngr = (rem + 7) & ~7;       // round up to groups of 8
        for (int g = 0; g < ngr; g += 8) {
            __half2 h;
            *(unsigned*)&h = 0u;
#pragma unroll
            for (int j = 0; j < 8; j++) {
                unsigned o = __shfl_sync(0xffffffffu, off, g + j);
                h = __hadd2(h, *(const __half2*)(basep + o));
            }
            float2 f = __half22float2(h);
            fa0 += f.x;
            fa1 += f.y;
        }
    }
    a0 = fa0;
    a1 = fa1;
}

__global__ void k_agg1(const float* __restrict__ b1) {
    int warp = (blockIdx.x * blockDim.x + threadIdx.x) >> 5;
    int lane = threadIdx.x & 31;
    if (warp >= NN) return;
    float a0, a1;
    agg_row(warp, lane, a0, a1);
    float dd = g_dinv[warp];
    float2 sv = __half22float2(g_xws[warp * (HID / 2) + lane]);
    float r0 = fmaxf(fmaf(dd, a0 + sv.x, b1[2 * lane + 0]), 0.f);
    float r1 = fmaxf(fmaf(dd, a1 + sv.y, b1[2 * lane + 1]), 0.f);
    g_h1[warp * (HID / 2) + lane] = __floats2half2_rn(r0, r1);
}

__global__ void k_agg2(const float* __restrict__ b2, const float* __restrict__ Wfc,
                       const float* __restrict__ bfc, float* __restrict__ out) {
    __shared__ float sW[HID * NCLS];
    __shared__ float sb2[HID];
    __shared__ float sbfc[NCLS];
    int tid = threadIdx.x;
    for (int i = tid; i < HID * NCLS; i += 256) sW[i] = Wfc[i];
    if (tid < HID)  sb2[tid]  = b2[tid];
    if (tid < NCLS) sbfc[tid] = bfc[tid];
    __syncthreads();

    int warp = (blockIdx.x * blockDim.x + tid) >> 5;
    int lane = tid & 31;
    if (warp >= NN) return;
    float a0, a1;
    agg_row(warp, lane, a0, a1);
    float dd = g_dinv[warp];
    float2 sv = __half22float2(g_xws[warp * (HID / 2) + lane]);
    float t0 = fmaxf(fmaf(dd, a0 + sv.x, sb2[2 * lane + 0]), 0.f);
    float t1 = fmaxf(fmaf(dd, a1 + sv.y, sb2[2 * lane + 1]), 0.f);

    float res = 0.f;
#pragma unroll
    for (int c = 0; c < NCLS; c++) {
        float p = t0 * sW[(2 * lane + 0) * NCLS + c] + t1 * sW[(2 * lane + 1) * NCLS + c];
        p += __shfl_xor_sync(0xffffffffu, p, 16);
        p += __shfl_xor_sync(0xffffffffu, p, 8);
        p += __shfl_xor_sync(0xffffffffu, p, 4);
        p += __shfl_xor_sync(0xffffffffu, p, 2);
        p += __shfl_xor_sync(0xffffffffu, p, 1);
        if (lane == c) res = p + sbfc[c];
    }
    if (lane < NCLS) out[warp * NCLS + lane] = res;
}

// ---------------- launch -----------------------------------------------------
extern "C" void kernel_launch(void* const* d_in, const int* in_sizes, int n_in,
                              void* d_out, int out_size) {
    const float* x   = (const float*)d_in[0];
    const int*   ei  = (const int*)d_in[1];   // int32 (JAX x64-disabled)
    const float* W1  = (const float*)d_in[2];
    const float* b1  = (const float*)d_in[3];
    const float* W2  = (const float*)d_in[4];
    const float* b2  = (const float*)d_in[5];
    const float* Wfc = (const float*)d_in[6];
    const float* bfc = (const float*)d_in[7];
    float* out = (float*)d_out;
    const int* srcp = ei;
    const int* dstp = ei + NE;

    k_count<<<FBLK + 1, 256>>>(dstp, W1, W2);        // count + W->fp16
    k_scan<<<SB, 1024>>>();
    k_fillgemm<<<GB1 + FBLK, 256>>>(srcp, dstp, x);  // gemm1 ∥ CSR fill
    k_agg1<<<(NN + 7) / 8, 256>>>(b1);               // -> g_h1 (fp16)
    k_gemm2<<<GB1, 256>>>();                         // -> g_xws (fp16)
    k_agg2<<<(NN + 7) / 8, 256>>>(b2, Wfc, bfc, out);
}

// round 14
// speedup vs baseline: 1.2834x; 1.0389x over previous
#include <cuda_runtime.h>
#include <cuda_fp16.h>

#define NN 50000
#define NE 800000
#define FEAT 128
#define HID 64
#define NCLS 12
#define SB 49                         // scan blocks (1024 nodes each)
#define GB1 ((NN + 63) / 64)          // gemm1 blocks: 782
#define FBLK ((NE + 255) / 256)       // fill blocks: 3125
#define ZOFF ((unsigned)(NN * 128))   // byte offset of the always-zero pad row

// ---------------- scratch (static device globals; zero-initialized) ----------
__device__ __align__(16) int      g_deg[NN];                 // zero-invariant
__device__ __align__(16) unsigned long long g_state[SB];     // zero-invariant
__device__ __align__(16) int      g_rowptr[NN + 1];
__device__ __align__(16) int      g_cursor[NN];
__device__ __align__(16) unsigned g_csrb[NE];                // src row BYTE offsets
__device__ __align__(16) float    g_dinv[NN];
__device__ __align__(16) __half2  g_xws[(NN + 1) * (HID / 2)]; // +1 zero pad row
__device__ __align__(16) __half2  g_h1[NN * (HID / 2)];      // layer-1 activations
__device__ __align__(16) __half   g_w1t[64 * FEAT];          // W1^T fp16 (n-major)
__device__ __align__(16) __half   g_w2t[64 * HID];           // W2^T fp16 (n-major)

// ---------------- CSR count + weight conversion ------------------------------
__global__ void k_count(const int* __restrict__ dst,
                        const float* __restrict__ W1, const float* __restrict__ W2) {
    int b = blockIdx.x;
    if (b == gridDim.x - 1) {            // extra block: convert weights to fp16 n-major
        for (int i = threadIdx.x; i < 64 * FEAT; i += 256) {
            int n = i / FEAT, k = i % FEAT;
            g_w1t[i] = __float2half(W1[k * 64 + n]);
        }
        for (int i = threadIdx.x; i < 64 * HID; i += 256) {
            int n = i / HID, k = i % HID;
            g_w2t[i] = __float2half(W2[k * 64 + n]);
        }
        return;
    }
    int e = b * 256 + threadIdx.x;
    if (e < NE) atomicAdd(&g_deg[dst[e]], 1);
}

__device__ __forceinline__ int block_excl_scan(int v, int* sm32) {
    int lane = threadIdx.x & 31, wid = threadIdx.x >> 5;
    int incl = v;
#pragma unroll
    for (int d = 1; d < 32; d <<= 1) {
        int n = __shfl_up_sync(0xffffffffu, incl, d);
        if (lane >= d) incl += n;
    }
    if (lane == 31) sm32[wid] = incl;
    __syncthreads();
    if (wid == 0) {
        int w = sm32[lane];
#pragma unroll
        for (int d = 1; d < 32; d <<= 1) {
            int n = __shfl_up_sync(0xffffffffu, w, d);
            if (lane >= d) w += n;
        }
        sm32[lane] = w;
    }
    __syncthreads();
    int off = wid ? sm32[wid - 1] : 0;
    return incl - v + off;
}

// single-pass scan via decoupled aggregates
__global__ void __launch_bounds__(1024)
k_scan() {
    __shared__ int sm32[32];
    __shared__ int s_base;
    int tid = threadIdx.x, b = blockIdx.x;
    int i = b * 1024 + tid;
    int v = (i < NN) ? g_deg[i] : 0;
    int excl = block_excl_scan(v, sm32);
    if (tid == 1023) {
        unsigned long long st = (1ULL << 32) | (unsigned)(excl + v);
        atomicExch(&g_state[b], st);
    }
    if (tid < 32) {
        unsigned sum = 0;
        for (int j = tid; j < b; j += 32) {
            unsigned long long s;
            do { s = atomicAdd(&g_state[j], 0ULL); } while (!(s >> 32));
            sum += (unsigned)s;
        }
#pragma unroll
        for (int d = 16; d; d >>= 1) sum += __shfl_xor_sync(0xffffffffu, sum, d);
        if (tid == 0) s_base = (int)sum;
    }
    __syncthreads();
    if (i < NN) {
        int run = s_base + excl;
        g_rowptr[i] = run;
        g_cursor[i] = run;
        g_dinv[i]   = rsqrtf((float)v + 1.0f);
    }
    if (b == 0 && tid == 0) g_rowptr[NN] = NE;
}

// ---------------- mma / ldmatrix helpers -------------------------------------
__device__ __forceinline__ void mma16816(float c[4],
                                         unsigned a0, unsigned a1, unsigned a2, unsigned a3,
                                         unsigned b0, unsigned b1) {
    asm volatile(
        "mma.sync.aligned.m16n8k16.row.col.f32.f16.f16.f32 "
        "{%0,%1,%2,%3}, {%4,%5,%6,%7}, {%8,%9}, {%0,%1,%2,%3};\n"
        : "+f"(c[0]), "+f"(c[1]), "+f"(c[2]), "+f"(c[3])
        : "r"(a0), "r"(a1), "r"(a2), "r"(a3), "r"(b0), "r"(b1));
}

__device__ __forceinline__ void ldsm4(unsigned& a0, unsigned& a1,
                                      unsigned& a2, unsigned& a3, unsigned addr) {
    asm volatile(
        "ldmatrix.sync.aligned.m8n8.x4.shared.b16 {%0,%1,%2,%3}, [%4];\n"
        : "=r"(a0), "=r"(a1), "=r"(a2), "=r"(a3) : "r"(addr));
}

// ---------------- GEMM1 body (x @ W1)*dinv, full-prefetch both K-chunks ------
__device__ __forceinline__ void gemm1_body(const float* __restrict__ Aext, int bidx) {
    const int K = FEAT;
    const int KP = 64 + 8;
    __shared__ __half Ah[64 * KP];
    int tid = threadIdx.x;
    int lane = tid & 31, warp = tid >> 5;
    int row0 = bidx * 64;
    int gid = lane >> 2, tig = lane & 3;
    int n0 = warp * 8;

    float4 vf[8];
#pragma unroll
    for (int p = 0; p < 8; p++) {
        int i = tid + (p & 3) * 256;
        int r = i >> 4, c4 = i & 15;
        int col = (p >> 2) * 64 + c4 * 4;
        vf[p] = (row0 + r < NN)
            ? *(const float4*)&Aext[(size_t)(row0 + r) * K + col]
            : make_float4(0.f, 0.f, 0.f, 0.f);
    }

    unsigned bf[8][2];
#pragma unroll
    for (int kk = 0; kk < 8; kk++) {
        const __half* wb = &g_w1t[(n0 + gid) * K + kk * 16 + tig * 2];
        bf[kk][0] = *(const unsigned*)wb;
        bf[kk][1] = *(const unsigned*)(wb + 8);
    }

    float cacc[4][4];
#pragma unroll
    for (int r = 0; r < 4; r++)
        cacc[r][0] = cacc[r][1] = cacc[r][2] = cacc[r][3] = 0.f;

    unsigned abase = (unsigned)__cvta_generic_to_shared(
        &Ah[(lane & 15) * KP + (lane >> 4) * 8]);

#pragma unroll
    for (int ch = 0; ch < 2; ch++) {
        if (ch) __syncthreads();
#pragma unroll
        for (int p = 0; p < 4; p++) {
            int i = tid + p * 256;
            int r = i >> 4, c4 = i & 15;
            float4 v = vf[ch * 4 + p];
            __half2 h0 = __floats2half2_rn(v.x, v.y);
            __half2 h1 = __floats2half2_rn(v.z, v.w);
            *(unsigned*)&Ah[r * KP + c4 * 4]     = *(unsigned*)&h0;
            *(unsigned*)&Ah[r * KP + c4 * 4 + 2] = *(unsigned*)&h1;
        }
        __syncthreads();
#pragma unroll
        for (int kk = 0; kk < 4; kk++) {
            int kf = ch * 4 + kk;
            int kl = kk * 16;
#pragma unroll
            for (int rt = 0; rt < 4; rt++) {
                unsigned a0, a1, a2, a3;
                ldsm4(a0, a1, a2, a3,
                      abase + (unsigned)((rt * 16 * KP + kl) * sizeof(__half)));
                mma16816(cacc[rt], a0, a1, a2, a3, bf[kf][0], bf[kf][1]);
            }
        }
    }

#pragma unroll
    for (int rt = 0; rt < 4; rt++) {
        int r0 = row0 + rt * 16 + gid;
        int r1 = r0 + 8;
        if (r0 < NN) {
            float dv = g_dinv[r0];
            g_xws[r0 * 32 + n0 / 2 + tig] =
                __floats2half2_rn(cacc[rt][0] * dv, cacc[rt][1] * dv);
        }
        if (r1 < NN) {
            float dv = g_dinv[r1];
            g_xws[r1 * 32 + n0 / 2 + tig] =
                __floats2half2_rn(cacc[rt][2] * dv, cacc[rt][3] * dv);
        }
    }
}

// ---------------- merged: gemm1 blocks + CSR-fill blocks ---------------------
__global__ void __launch_bounds__(256)
k_fillgemm(const int* __restrict__ src, const int* __restrict__ dst,
           const float* __restrict__ x) {
    if (blockIdx.x < GB1) {
        gemm1_body(x, blockIdx.x);
        return;
    }
    int e = (blockIdx.x - GB1) * 256 + threadIdx.x;
    if (e < NN) g_deg[e] = 0;           // restore zero-invariants
    if (e < SB) g_state[e] = 0ULL;
    if (e < NE) {
        int d = dst[e];
        int pos = atomicAdd(&g_cursor[d], 1);
        g_csrb[pos] = (unsigned)src[e] * 128u;   // BYTE offset of src row
    }
}

// ---------------- GEMM2: g_xws = (h1 @ W2) * dinv ---------------------------
__global__ void __launch_bounds__(256)
k_gemm2() {
    const int K = HID;
    const int KP = 64 + 8;
    __shared__ __half Ah[64 * KP];
    int tid = threadIdx.x;
    int lane = tid & 31, warp = tid >> 5;
    int row0 = blockIdx.x * 64;
    int gid = lane >> 2, tig = lane & 3;
    int n0 = warp * 8;

    unsigned vh[8];
#pragma unroll
    for (int p = 0; p < 8; p++) {
        int i = tid + p * 256;
        int r = i >> 5, c = i & 31;
        vh[p] = (row0 + r < NN) ? *(const unsigned*)&g_h1[(row0 + r) * 32 + c] : 0u;
    }

    unsigned bf[4][2];
#pragma unroll
    for (int kk = 0; kk < 4; kk++) {
        const __half* wb = &g_w2t[(n0 + gid) * K + kk * 16 + tig * 2];
        bf[kk][0] = *(const unsigned*)wb;
        bf[kk][1] = *(const unsigned*)(wb + 8);
    }

    float cacc[4][4];
#pragma unroll
    for (int r = 0; r < 4; r++)
        cacc[r][0] = cacc[r][1] = cacc[r][2] = cacc[r][3] = 0.f;

#pragma unroll
    for (int p = 0; p < 8; p++) {
        int i = tid + p * 256;
        int r = i >> 5, c = i & 31;
        *(unsigned*)&Ah[r * KP + c * 2] = vh[p];
    }
    __syncthreads();

    unsigned abase = (unsigned)__cvta_generic_to_shared(
        &Ah[(lane & 15) * KP + (lane >> 4) * 8]);
#pragma unroll
    for (int kk = 0; kk < 4; kk++) {
        int kl = kk * 16;
#pragma unroll
        for (int rt = 0; rt < 4; rt++) {
            unsigned a0, a1, a2, a3;
            ldsm4(a0, a1, a2, a3,
                  abase + (unsigned)((rt * 16 * KP + kl) * sizeof(__half)));
            mma16816(cacc[rt], a0, a1, a2, a3, bf[kk][0], bf[kk][1]);
        }
    }

#pragma unroll
    for (int rt = 0; rt < 4; rt++) {
        int r0 = row0 + rt * 16 + gid;
        int r1 = r0 + 8;
        if (r0 < NN) {
            float dv = g_dinv[r0];
            g_xws[r0 * 32 + n0 / 2 + tig] =
                __floats2half2_rn(cacc[rt][0] * dv, cacc[rt][1] * dv);
        }
        if (r1 < NN) {
            float dv = g_dinv[r1];
            g_xws[r1 * 32 + n0 / 2 + tig] =
                __floats2half2_rn(cacc[rt][2] * dv, cacc[rt][3] * dv);
        }
    }
}

// ---------------- aggregation: 4 edges/instruction ---------------------------
// Warp = 4 groups x 8 lanes. Lane covers 16B feature slice (fl*16); one LDG.128
// fetches 4 full rows (4 edges). fp16 depth-8 accumulate, fp32 flush per block.
// Cross-group partials folded by shfl_xor(8,16). facc[j] = feats fl*8+j.
__device__ __forceinline__ void agg_row8(int node, int lane, float facc[8]) {
    int beg = g_rowptr[node];
    int end = g_rowptr[node + 1];
    int grp = lane >> 3;
    unsigned fb = (unsigned)((lane & 7) * 16);
    const char* base = (const char*)g_xws;
#pragma unroll
    for (int j = 0; j < 8; j++) facc[j] = 0.f;
    for (int b32 = beg; b32 < end; b32 += 32) {
        int idx = b32 + lane;
        unsigned off = (idx < end) ? g_csrb[idx] : ZOFF;
        int rem = end - b32;
        if (rem > 32) rem = 32;
        int nb = (rem + 3) >> 2;            // bundles of 4 edges
        __half2 h[4];
#pragma unroll
        for (int j = 0; j < 4; j++) *(unsigned*)&h[j] = 0u;
        for (int t = 0; t < nb; t++) {
            unsigned o = __shfl_sync(0xffffffffu, off, t * 4 + grp);
            uint4 v = *(const uint4*)(base + o + fb);
            h[0] = __hadd2(h[0], *(__half2*)&v.x);
            h[1] = __hadd2(h[1], *(__half2*)&v.y);
            h[2] = __hadd2(h[2], *(__half2*)&v.z);
            h[3] = __hadd2(h[3], *(__half2*)&v.w);
        }
#pragma unroll
        for (int j = 0; j < 4; j++) {
            float2 f = __half22float2(h[j]);
            facc[2 * j]     += f.x;
            facc[2 * j + 1] += f.y;
        }
    }
#pragma unroll
    for (int j = 0; j < 8; j++) {
        facc[j] += __shfl_xor_sync(0xffffffffu, facc[j], 8);
        facc[j] += __shfl_xor_sync(0xffffffffu, facc[j], 16);
    }
}

__global__ void k_agg1(const float* __restrict__ b1) {
    int warp = (blockIdx.x * blockDim.x + threadIdx.x) >> 5;
    int lane = threadIdx.x & 31;
    if (warp >= NN) return;
    float f[8];
    agg_row8(warp, lane, f);
    float dd = g_dinv[warp];
    int fl = lane & 7;
    uint4 sv = *(const uint4*)((const char*)g_xws + (unsigned)warp * 128u + (unsigned)(fl * 16));
    __half2* sh = (__half2*)&sv;
    float4 bb0 = *(const float4*)(b1 + fl * 8);
    float4 bb1 = *(const float4*)(b1 + fl * 8 + 4);
    float bb[8] = {bb0.x, bb0.y, bb0.z, bb0.w, bb1.x, bb1.y, bb1.z, bb1.w};
    __half2 oh[4];
#pragma unroll
    for (int j = 0; j < 4; j++) {
        float2 s = __half22float2(sh[j]);
        float r0 = fmaxf(fmaf(dd, f[2 * j] + s.x,     bb[2 * j]),     0.f);
        float r1 = fmaxf(fmaf(dd, f[2 * j + 1] + s.y, bb[2 * j + 1]), 0.f);
        oh[j] = __floats2half2_rn(r0, r1);
    }
    if (lane < 8)
        *(uint4*)((char*)g_h1 + (unsigned)warp * 128u + (unsigned)(fl * 16)) = *(uint4*)oh;
}

// layer-2 aggregation + FC: group g computes classes 3g..3g+2 (pitch-13 sW).
__global__ void k_agg2(const float* __restrict__ b2, const float* __restrict__ Wfc,
                       const float* __restrict__ bfc, float* __restrict__ out) {
    __shared__ float sW[HID * 13];
    __shared__ float sb2[HID];
    __shared__ float sbfc[NCLS];
    int tid = threadIdx.x;
    for (int i = tid; i < HID * NCLS; i += 256) {
        int fi = i / NCLS, c = i % NCLS;
        sW[fi * 13 + c] = Wfc[i];
    }
    if (tid < HID)  sb2[tid]  = b2[tid];
    if (tid < NCLS) sbfc[tid] = bfc[tid];
    __syncthreads();

    int warp = (blockIdx.x * blockDim.x + tid) >> 5;
    int lane = tid & 31;
    if (warp >= NN) return;
    float f[8];
    agg_row8(warp, lane, f);
    float dd = g_dinv[warp];
    int fl = lane & 7, grp = lane >> 3;
    uint4 sv = *(const uint4*)((const char*)g_xws + (unsigned)warp * 128u + (unsigned)(fl * 16));
    __half2* sh = (__half2*)&sv;
    float t[8];
#pragma unroll
    for (int j = 0; j < 4; j++) {
        float2 s = __half22float2(sh[j]);
        t[2 * j]     = fmaxf(fmaf(dd, f[2 * j] + s.x,     sb2[fl * 8 + 2 * j]),     0.f);
        t[2 * j + 1] = fmaxf(fmaf(dd, f[2 * j + 1] + s.y, sb2[fl * 8 + 2 * j + 1]), 0.f);
    }
#pragma unroll
    for (int k = 0; k < 3; k++) {
        int c = 3 * grp + k;
        float p = 0.f;
#pragma unroll
        for (int j = 0; j < 8; j++)
            p = fmaf(t[j], sW[(fl * 8 + j) * 13 + c], p);
        p += __shfl_xor_sync(0xffffffffu, p, 1);
        p += __shfl_xor_sync(0xffffffffu, p, 2);
        p += __shfl_xor_sync(0xffffffffu, p, 4);
        if (fl == 0) out[(size_t)warp * NCLS + c] = p + sbfc[c];
    }
}

// ---------------- launch -----------------------------------------------------
extern "C" void kernel_launch(void* const* d_in, const int* in_sizes, int n_in,
                              void* d_out, int out_size) {
    const float* x   = (const float*)d_in[0];
    const int*   ei  = (const int*)d_in[1];   // int32 (JAX x64-disabled)
    const float* W1  = (const float*)d_in[2];
    const float* b1  = (const float*)d_in[3];
    const float* W2  = (const float*)d_in[4];
    const float* b2  = (const float*)d_in[5];
    const float* Wfc = (const float*)d_in[6];
    const float* bfc = (const float*)d_in[7];
    float* out = (float*)d_out;
    const int* srcp = ei;
    const int* dstp = ei + NE;

    k_count<<<FBLK + 1, 256>>>(dstp, W1, W2);        // count + W->fp16
    k_scan<<<SB, 1024>>>();
    k_fillgemm<<<GB1 + FBLK, 256>>>(srcp, dstp, x);  // gemm1 ∥ CSR fill
    k_agg1<<<(NN + 7) / 8, 256>>>(b1);               // -> g_h1 (fp16)
    k_gemm2<<<GB1, 256>>>();                         // -> g_xws (fp16)
    k_agg2<<<(NN + 7) / 8, 256>>>(b2, Wfc, bfc, out);
}

// round 15
// speedup vs baseline: 1.3377x; 1.0423x over previous
#include <cuda_runtime.h>
#include <cuda_fp16.h>

#define NN 50000
#define NE 800000
#define FEAT 128
#define HID 64
#define NCLS 12
#define SB 49                         // scan blocks (1024 nodes each)
#define GB1 ((NN + 63) / 64)          // gemm1 blocks: 782
#define FBLK ((NE + 255) / 256)       // fill blocks: 3125
#define ZOFF ((unsigned)(NN * 128))   // byte offset of the always-zero pad row

// ---------------- scratch (static device globals; zero-initialized) ----------
__device__ __align__(16) int      g_deg[NN];                 // zero-invariant
__device__ __align__(16) unsigned long long g_state[SB];     // zero-invariant
__device__ __align__(16) int      g_rowptr[NN + 1];
__device__ __align__(16) int      g_cursor[NN];
__device__ __align__(16) unsigned g_csrb[NE];                // src row BYTE offsets
__device__ __align__(16) float    g_dinv[NN];
__device__ __align__(16) __half2  g_xws[(NN + 1) * (HID / 2)]; // +1 zero pad row
__device__ __align__(16) __half2  g_h1[NN * (HID / 2)];      // layer-1 activations
__device__ __align__(16) __half   g_w1t[64 * FEAT];          // W1^T fp16 (n-major)
__device__ __align__(16) __half   g_w2t[64 * HID];           // W2^T fp16 (n-major)

// ---------------- CSR count + weight conversion ------------------------------
__global__ void k_count(const int* __restrict__ dst,
                        const float* __restrict__ W1, const float* __restrict__ W2) {
    int b = blockIdx.x;
    if (b == gridDim.x - 1) {            // extra block: convert weights to fp16 n-major
        for (int i = threadIdx.x; i < 64 * FEAT; i += 256) {
            int n = i / FEAT, k = i % FEAT;
            g_w1t[i] = __float2half(W1[k * 64 + n]);
        }
        for (int i = threadIdx.x; i < 64 * HID; i += 256) {
            int n = i / HID, k = i % HID;
            g_w2t[i] = __float2half(W2[k * 64 + n]);
        }
        return;
    }
    int e = b * 256 + threadIdx.x;
    if (e < NE) atomicAdd(&g_deg[dst[e]], 1);
}

__device__ __forceinline__ int block_excl_scan(int v, int* sm32) {
    int lane = threadIdx.x & 31, wid = threadIdx.x >> 5;
    int incl = v;
#pragma unroll
    for (int d = 1; d < 32; d <<= 1) {
        int n = __shfl_up_sync(0xffffffffu, incl, d);
        if (lane >= d) incl += n;
    }
    if (lane == 31) sm32[wid] = incl;
    __syncthreads();
    if (wid == 0) {
        int w = sm32[lane];
#pragma unroll
        for (int d = 1; d < 32; d <<= 1) {
            int n = __shfl_up_sync(0xffffffffu, w, d);
            if (lane >= d) w += n;
        }
        sm32[lane] = w;
    }
    __syncthreads();
    int off = wid ? sm32[wid - 1] : 0;
    return incl - v + off;
}

// single-pass scan via decoupled aggregates
__global__ void __launch_bounds__(1024)
k_scan() {
    __shared__ int sm32[32];
    __shared__ int s_base;
    int tid = threadIdx.x, b = blockIdx.x;
    int i = b * 1024 + tid;
    int v = (i < NN) ? g_deg[i] : 0;
    int excl = block_excl_scan(v, sm32);
    if (tid == 1023) {
        unsigned long long st = (1ULL << 32) | (unsigned)(excl + v);
        atomicExch(&g_state[b], st);
    }
    if (tid < 32) {
        unsigned sum = 0;
        for (int j = tid; j < b; j += 32) {
            unsigned long long s;
            do { s = atomicAdd(&g_state[j], 0ULL); } while (!(s >> 32));
            sum += (unsigned)s;
        }
#pragma unroll
        for (int d = 16; d; d >>= 1) sum += __shfl_xor_sync(0xffffffffu, sum, d);
        if (tid == 0) s_base = (int)sum;
    }
    __syncthreads();
    if (i < NN) {
        int run = s_base + excl;
        g_rowptr[i] = run;
        g_cursor[i] = run;
        g_dinv[i]   = rsqrtf((float)v + 1.0f);
    }
    if (b == 0 && tid == 0) g_rowptr[NN] = NE;
}

// ---------------- mma / ldmatrix helpers -------------------------------------
__device__ __forceinline__ void mma16816(float c[4],
                                         unsigned a0, unsigned a1, unsigned a2, unsigned a3,
                                         unsigned b0, unsigned b1) {
    asm volatile(
        "mma.sync.aligned.m16n8k16.row.col.f32.f16.f16.f32 "
        "{%0,%1,%2,%3}, {%4,%5,%6,%7}, {%8,%9}, {%0,%1,%2,%3};\n"
        : "+f"(c[0]), "+f"(c[1]), "+f"(c[2]), "+f"(c[3])
        : "r"(a0), "r"(a1), "r"(a2), "r"(a3), "r"(b0), "r"(b1));
}

__device__ __forceinline__ void ldsm4(unsigned& a0, unsigned& a1,
                                      unsigned& a2, unsigned& a3, unsigned addr) {
    asm volatile(
        "ldmatrix.sync.aligned.m8n8.x4.shared.b16 {%0,%1,%2,%3}, [%4];\n"
        : "=r"(a0), "=r"(a1), "=r"(a2), "=r"(a3) : "r"(addr));
}

// ---------------- GEMM1 body (x @ W1)*dinv, full-prefetch both K-chunks ------
__device__ __forceinline__ void gemm1_body(const float* __restrict__ Aext, int bidx) {
    const int K = FEAT;
    const int KP = 64 + 8;
    __shared__ __half Ah[64 * KP];
    int tid = threadIdx.x;
    int lane = tid & 31, warp = tid >> 5;
    int row0 = bidx * 64;
    int gid = lane >> 2, tig = lane & 3;
    int n0 = warp * 8;

    float4 vf[8];
#pragma unroll
    for (int p = 0; p < 8; p++) {
        int i = tid + (p & 3) * 256;
        int r = i >> 4, c4 = i & 15;
        int col = (p >> 2) * 64 + c4 * 4;
        vf[p] = (row0 + r < NN)
            ? *(const float4*)&Aext[(size_t)(row0 + r) * K + col]
            : make_float4(0.f, 0.f, 0.f, 0.f);
    }

    unsigned bf[8][2];
#pragma unroll
    for (int kk = 0; kk < 8; kk++) {
        const __half* wb = &g_w1t[(n0 + gid) * K + kk * 16 + tig * 2];
        bf[kk][0] = *(const unsigned*)wb;
        bf[kk][1] = *(const unsigned*)(wb + 8);
    }

    float cacc[4][4];
#pragma unroll
    for (int r = 0; r < 4; r++)
        cacc[r][0] = cacc[r][1] = cacc[r][2] = cacc[r][3] = 0.f;

    unsigned abase = (unsigned)__cvta_generic_to_shared(
        &Ah[(lane & 15) * KP + (lane >> 4) * 8]);

#pragma unroll
    for (int ch = 0; ch < 2; ch++) {
        if (ch) __syncthreads();
#pragma unroll
        for (int p = 0; p < 4; p++) {
            int i = tid + p * 256;
            int r = i >> 4, c4 = i & 15;
            float4 v = vf[ch * 4 + p];
            __half2 h0 = __floats2half2_rn(v.x, v.y);
            __half2 h1 = __floats2half2_rn(v.z, v.w);
            *(unsigned*)&Ah[r * KP + c4 * 4]     = *(unsigned*)&h0;
            *(unsigned*)&Ah[r * KP + c4 * 4 + 2] = *(unsigned*)&h1;
        }
        __syncthreads();
#pragma unroll
        for (int kk = 0; kk < 4; kk++) {
            int kf = ch * 4 + kk;
            int kl = kk * 16;
#pragma unroll
            for (int rt = 0; rt < 4; rt++) {
                unsigned a0, a1, a2, a3;
                ldsm4(a0, a1, a2, a3,
                      abase + (unsigned)((rt * 16 * KP + kl) * sizeof(__half)));
                mma16816(cacc[rt], a0, a1, a2, a3, bf[kf][0], bf[kf][1]);
            }
        }
    }

#pragma unroll
    for (int rt = 0; rt < 4; rt++) {
        int r0 = row0 + rt * 16 + gid;
        int r1 = r0 + 8;
        if (r0 < NN) {
            float dv = g_dinv[r0];
            g_xws[r0 * 32 + n0 / 2 + tig] =
                __floats2half2_rn(cacc[rt][0] * dv, cacc[rt][1] * dv);
        }
        if (r1 < NN) {
            float dv = g_dinv[r1];
            g_xws[r1 * 32 + n0 / 2 + tig] =
                __floats2half2_rn(cacc[rt][2] * dv, cacc[rt][3] * dv);
        }
    }
}

// ---------------- merged: gemm1 blocks + CSR-fill blocks ---------------------
__global__ void __launch_bounds__(256)
k_fillgemm(const int* __restrict__ src, const int* __restrict__ dst,
           const float* __restrict__ x) {
    if (blockIdx.x < GB1) {
        gemm1_body(x, blockIdx.x);
        return;
    }
    int e = (blockIdx.x - GB1) * 256 + threadIdx.x;
    if (e < NN) g_deg[e] = 0;           // restore zero-invariants
    if (e < SB) g_state[e] = 0ULL;
    if (e < NE) {
        int d = dst[e];
        int pos = atomicAdd(&g_cursor[d], 1);
        g_csrb[pos] = (unsigned)src[e] * 128u;   // BYTE offset of src row
    }
}

// ---------------- GEMM2: g_xws = (h1 @ W2) * dinv ---------------------------
__global__ void __launch_bounds__(256)
k_gemm2() {
    const int K = HID;
    const int KP = 64 + 8;
    __shared__ __half Ah[64 * KP];
    int tid = threadIdx.x;
    int lane = tid & 31, warp = tid >> 5;
    int row0 = blockIdx.x * 64;
    int gid = lane >> 2, tig = lane & 3;
    int n0 = warp * 8;

    unsigned vh[8];
#pragma unroll
    for (int p = 0; p < 8; p++) {
        int i = tid + p * 256;
        int r = i >> 5, c = i & 31;
        vh[p] = (row0 + r < NN) ? *(const unsigned*)&g_h1[(row0 + r) * 32 + c] : 0u;
    }

    unsigned bf[4][2];
#pragma unroll
    for (int kk = 0; kk < 4; kk++) {
        const __half* wb = &g_w2t[(n0 + gid) * K + kk * 16 + tig * 2];
        bf[kk][0] = *(const unsigned*)wb;
        bf[kk][1] = *(const unsigned*)(wb + 8);
    }

    float cacc[4][4];
#pragma unroll
    for (int r = 0; r < 4; r++)
        cacc[r][0] = cacc[r][1] = cacc[r][2] = cacc[r][3] = 0.f;

#pragma unroll
    for (int p = 0; p < 8; p++) {
        int i = tid + p * 256;
        int r = i >> 5, c = i & 31;
        *(unsigned*)&Ah[r * KP + c * 2] = vh[p];
    }
    __syncthreads();

    unsigned abase = (unsigned)__cvta_generic_to_shared(
        &Ah[(lane & 15) * KP + (lane >> 4) * 8]);
#pragma unroll
    for (int kk = 0; kk < 4; kk++) {
        int kl = kk * 16;
#pragma unroll
        for (int rt = 0; rt < 4; rt++) {
            unsigned a0, a1, a2, a3;
            ldsm4(a0, a1, a2, a3,
                  abase + (unsigned)((rt * 16 * KP + kl) * sizeof(__half)));
            mma16816(cacc[rt], a0, a1, a2, a3, bf[kk][0], bf[kk][1]);
        }
    }

#pragma unroll
    for (int rt = 0; rt < 4; rt++) {
        int r0 = row0 + rt * 16 + gid;
        int r1 = r0 + 8;
        if (r0 < NN) {
            float dv = g_dinv[r0];
            g_xws[r0 * 32 + n0 / 2 + tig] =
                __floats2half2_rn(cacc[rt][0] * dv, cacc[rt][1] * dv);
        }
        if (r1 < NN) {
            float dv = g_dinv[r1];
            g_xws[r1 * 32 + n0 / 2 + tig] =
                __floats2half2_rn(cacc[rt][2] * dv, cacc[rt][3] * dv);
        }
    }
}

// ---------------- agg variant A (R13): lane = 2 feats, LDG.64 gather ---------
// Per-edge: SHFL + IADD + LDG.64 + HADD2; high occupancy (32 regs).
__device__ __forceinline__ void agg_row2(int node, int lane, float& a0, float& a1) {
    int beg = g_rowptr[node];
    int end = g_rowptr[node + 1];
    const char* basep = (const char*)g_xws + lane * 4;
    float fa0 = 0.f, fa1 = 0.f;
    for (int b32 = beg; b32 < end; b32 += 32) {
        int idx = b32 + lane;
        unsigned off = (idx < end) ? g_csrb[idx] : ZOFF;
        int rem = end - b32;
        if (rem > 32) rem = 32;
        int ngr = (rem + 7) & ~7;
        for (int g = 0; g < ngr; g += 8) {
            __half2 h;
            *(unsigned*)&h = 0u;
#pragma unroll
            for (int j = 0; j < 8; j++) {
                unsigned o = __shfl_sync(0xffffffffu, off, g + j);
                h = __hadd2(h, *(const __half2*)(basep + o));
            }
            float2 f = __half22float2(h);
            fa0 += f.x;
            fa1 += f.y;
        }
    }
    a0 = fa0;
    a1 = fa1;
}

__global__ void k_agg1(const float* __restrict__ b1) {
    int warp = (blockIdx.x * blockDim.x + threadIdx.x) >> 5;
    int lane = threadIdx.x & 31;
    if (warp >= NN) return;
    float a0, a1;
    agg_row2(warp, lane, a0, a1);
    float dd = g_dinv[warp];
    float2 sv = __half22float2(g_xws[warp * (HID / 2) + lane]);
    float r0 = fmaxf(fmaf(dd, a0 + sv.x, b1[2 * lane + 0]), 0.f);
    float r1 = fmaxf(fmaf(dd, a1 + sv.y, b1[2 * lane + 1]), 0.f);
    g_h1[warp * (HID / 2) + lane] = __floats2half2_rn(r0, r1);
}

// ---------------- agg variant B (R14): lane = 8 feats, LDG.128 gather --------
// Used by agg2 for its cheap grouped FC epilogue.
__device__ __forceinline__ void agg_row8(int node, int lane, float facc[8]) {
    int beg = g_rowptr[node];
    int end = g_rowptr[node + 1];
    int grp = lane >> 3;
    unsigned fb = (unsigned)((lane & 7) * 16);
    const char* base = (const char*)g_xws;
#pragma unroll
    for (int j = 0; j < 8; j++) facc[j] = 0.f;
    for (int b32 = beg; b32 < end; b32 += 32) {
        int idx = b32 + lane;
        unsigned off = (idx < end) ? g_csrb[idx] : ZOFF;
        int rem = end - b32;
        if (rem > 32) rem = 32;
        int nb = (rem + 3) >> 2;
        __half2 h[4];
#pragma unroll
        for (int j = 0; j < 4; j++) *(unsigned*)&h[j] = 0u;
        for (int t = 0; t < nb; t++) {
            unsigned o = __shfl_sync(0xffffffffu, off, t * 4 + grp);
            uint4 v = *(const uint4*)(base + o + fb);
            h[0] = __hadd2(h[0], *(__half2*)&v.x);
            h[1] = __hadd2(h[1], *(__half2*)&v.y);
            h[2] = __hadd2(h[2], *(__half2*)&v.z);
            h[3] = __hadd2(h[3], *(__half2*)&v.w);
        }
#pragma unroll
        for (int j = 0; j < 4; j++) {
            float2 f = __half22float2(h[j]);
            facc[2 * j]     += f.x;
            facc[2 * j + 1] += f.y;
        }
    }
#pragma unroll
    for (int j = 0; j < 8; j++) {
        facc[j] += __shfl_xor_sync(0xffffffffu, facc[j], 8);
        facc[j] += __shfl_xor_sync(0xffffffffu, facc[j], 16);
    }
}

// layer-2 aggregation + FC: group g computes classes 3g..3g+2 (pitch-13 sW).
__global__ void k_agg2(const float* __restrict__ b2, const float* __restrict__ Wfc,
                       const float* __restrict__ bfc, float* __restrict__ out) {
    __shared__ float sW[HID * 13];
    __shared__ float sb2[HID];
    __shared__ float sbfc[NCLS];
    int tid = threadIdx.x;
    for (int i = tid; i < HID * NCLS; i += 256) {
        int fi = i / NCLS, c = i % NCLS;
        sW[fi * 13 + c] = Wfc[i];
    }
    if (tid < HID)  sb2[tid]  = b2[tid];
    if (tid < NCLS) sbfc[tid] = bfc[tid];
    __syncthreads();

    int warp = (blockIdx.x * blockDim.x + tid) >> 5;
    int lane = tid & 31;
    if (warp >= NN) return;
    float f[8];
    agg_row8(warp, lane, f);
    float dd = g_dinv[warp];
    int fl = lane & 7, grp = lane >> 3;
    uint4 sv = *(const uint4*)((const char*)g_xws + (unsigned)warp * 128u + (unsigned)(fl * 16));
    __half2* sh = (__half2*)&sv;
    float t[8];
#pragma unroll
    for (int j = 0; j < 4; j++) {
        float2 s = __half22float2(sh[j]);
        t[2 * j]     = fmaxf(fmaf(dd, f[2 * j] + s.x,     sb2[fl * 8 + 2 * j]),     0.f);
        t[2 * j + 1] = fmaxf(fmaf(dd, f[2 * j + 1] + s.y, sb2[fl * 8 + 2 * j + 1]), 0.f);
    }
#pragma unroll
    for (int k = 0; k < 3; k++) {
        int c = 3 * grp + k;
        float p = 0.f;
#pragma unroll
        for (int j = 0; j < 8; j++)
            p = fmaf(t[j], sW[(fl * 8 + j) * 13 + c], p);
        p += __shfl_xor_sync(0xffffffffu, p, 1);
        p += __shfl_xor_sync(0xffffffffu, p, 2);
        p += __shfl_xor_sync(0xffffffffu, p, 4);
        if (fl == 0) out[(size_t)warp * NCLS + c] = p + sbfc[c];
    }
}

// ---------------- launch -----------------------------------------------------
extern "C" void kernel_launch(void* const* d_in, const int* in_sizes, int n_in,
                              void* d_out, int out_size) {
    const float* x   = (const float*)d_in[0];
    const int*   ei  = (const int*)d_in[1];   // int32 (JAX x64-disabled)
    const float* W1  = (const float*)d_in[2];
    const float* b1  = (const float*)d_in[3];
    const float* W2  = (const float*)d_in[4];
    const float* b2  = (const float*)d_in[5];
    const float* Wfc = (const float*)d_in[6];
    const float* bfc = (const float*)d_in[7];
    float* out = (float*)d_out;
    const int* srcp = ei;
    const int* dstp = ei + NE;

    k_count<<<FBLK + 1, 256>>>(dstp, W1, W2);        // count + W->fp16
    k_scan<<<SB, 1024>>>();
    k_fillgemm<<<GB1 + FBLK, 256>>>(srcp, dstp, x);  // gemm1 ∥ CSR fill
    k_agg1<<<(NN + 7) / 8, 256>>>(b1);               // -> g_h1 (fp16)
    k_gemm2<<<GB1, 256>>>();                         // -> g_xws (fp16)
    k_agg2<<<(NN + 7) / 8, 256>>>(b2, Wfc, bfc, out);
}